// round 4
// baseline (speedup 1.0000x reference)
#include <cuda_runtime.h>
#include <cuda_bf16.h>
#include <math.h>

#define D 128
#define C 64
#define ROWS_PER_TILE 128
#define THREADS_MAIN 512   // 16 warps, each owns 4 classes
#define GRID_MAIN 148
#define LAMBDA_PROTO 0.5f

// -------- device scratch (zero at module load; finalize re-zeroes) --------
__device__ float g_sums[C * D];
__device__ float g_counts[C];
__device__ float g_z2[C];
__device__ float g_ce;

// smem layout (floats):
//  s_x   : 2 * 128 * 128        = 131072 B
//  s_inv : 2 * 128              = 1024 B
//  s_z2  : 2 * 128              = 1024 B
//  s_lbl : 2 * 128 (int)        = 1024 B
//  s_red : 16                   = 64 B
#define SMEM_BYTES (131072 + 1024 + 1024 + 1024 + 64)

// ---------------------------------------------------------
__device__ __forceinline__ void stage_tile_async(
    const float* __restrict__ emb, const unsigned int* __restrict__ lab_w,
    int lbl64, int row0, int nrows,
    float* s_x_buf, int* s_lbl_buf, int tid)
{
    const float4* g = (const float4*)(emb + (size_t)row0 * D);
    unsigned int dstx = (unsigned int)__cvta_generic_to_shared(s_x_buf);
    if (nrows == ROWS_PER_TILE) {
        #pragma unroll
        for (int k = 0; k < ROWS_PER_TILE * (D / 4) / THREADS_MAIN; ++k) {
            int i = tid + k * THREADS_MAIN;
            asm volatile("cp.async.cg.shared.global [%0], [%1], 16;\n"
                         :: "r"(dstx + i * 16), "l"(g + i));
        }
    } else {
        int nf4 = nrows * (D / 4);
        for (int i = tid; i < nf4; i += THREADS_MAIN) {
            asm volatile("cp.async.cg.shared.global [%0], [%1], 16;\n"
                         :: "r"(dstx + i * 16), "l"(g + i));
        }
    }
    if (tid < nrows) {
        const unsigned int* src = lab_w + (lbl64 ? 2 * (row0 + tid) : (row0 + tid));
        unsigned int dstl = (unsigned int)__cvta_generic_to_shared(s_lbl_buf + tid);
        asm volatile("cp.async.ca.shared.global [%0], [%1], 4;\n"
                     :: "r"(dstl), "l"(src));
    }
}

// ---------------------------------------------------------
__global__ __launch_bounds__(THREADS_MAIN, 1)
void fused_kernel(const float* __restrict__ emb,
                  const float* __restrict__ logits,
                  const unsigned int* __restrict__ lab_w, int N)
{
    extern __shared__ float smem[];
    float* s_x   = smem;                                      // [2][128*128]
    float* s_inv = smem + 2 * ROWS_PER_TILE * D;              // [2][128]
    float* s_z2  = s_inv + 2 * ROWS_PER_TILE;                 // [2][128]
    int*   s_lbl = (int*)(s_z2 + 2 * ROWS_PER_TILE);          // [2][128]
    float* s_red = (float*)(s_lbl + 2 * ROWS_PER_TILE);       // [16]

    const int tid  = threadIdx.x;
    const int wid  = tid >> 5;
    const int lane = tid & 31;
    const int base = wid * 4;          // warp owns classes [base, base+4)

    // --- per-warp label dtype detection (no sync needed) ---
    // int64 labels in [0,64): every odd 32-bit word is 0.
    // int32 random labels: P(32 odd words all zero) = 64^-32.
    unsigned probe = lab_w[2 * lane + 1];
    int lbl64 = (__ballot_sync(0xffffffffu, probe != 0u) == 0u);

    float4 a0 = {0,0,0,0}, a1 = a0, a2 = a0, a3 = a0;
    float  c0 = 0, c1 = 0, c2 = 0, c3 = 0;
    float  q0 = 0, q1 = 0, q2 = 0, q3 = 0;

    const int ntiles = (N + ROWS_PER_TILE - 1) / ROWS_PER_TILE;

    int tile = blockIdx.x;
    if (tile < ntiles) {
        int row0 = tile * ROWS_PER_TILE;
        stage_tile_async(emb, lab_w, lbl64, row0,
                         min(ROWS_PER_TILE, N - row0), s_x, s_lbl, tid);
    }
    asm volatile("cp.async.commit_group;\n" ::: "memory");

    int parity = 0;
    for (; tile < ntiles; tile += GRID_MAIN) {
        int nt = tile + GRID_MAIN;
        if (nt < ntiles) {
            int nrow0 = nt * ROWS_PER_TILE;
            stage_tile_async(emb, lab_w, lbl64, nrow0,
                             min(ROWS_PER_TILE, N - nrow0),
                             s_x + (parity ^ 1) * ROWS_PER_TILE * D,
                             s_lbl + (parity ^ 1) * ROWS_PER_TILE, tid);
        }
        asm volatile("cp.async.commit_group;\n" ::: "memory");
        asm volatile("cp.async.wait_group 1;\n" ::: "memory");
        __syncthreads();

        const int nrows = min(ROWS_PER_TILE, N - tile * ROWS_PER_TILE);
        float* sx  = s_x   + parity * ROWS_PER_TILE * D;
        float* siv = s_inv + parity * ROWS_PER_TILE;
        float* sz2 = s_z2  + parity * ROWS_PER_TILE;
        int*   slb = s_lbl + parity * ROWS_PER_TILE;

        // ---- parallel norm phase: 4 threads per row, all 128 rows at once ----
        {
            int r = tid >> 2;          // row 0..127
            int q = tid & 3;           // quarter
            if (r < nrows) {
                const float4* rp = (const float4*)&sx[r * D] + q * 8;
                float s = 0.0f;
                #pragma unroll
                for (int i = 0; i < 8; ++i) {
                    float4 v = rp[i];
                    s += v.x*v.x + v.y*v.y + v.z*v.z + v.w*v.w;
                }
                s += __shfl_xor_sync(0xffffffffu, s, 1);
                s += __shfl_xor_sync(0xffffffffu, s, 2);
                if (q == 0) {
                    float inv = rsqrtf(fmaxf(s, 1e-24f));  // == 1/max(||x||,1e-12)
                    siv[r] = inv;
                    sz2[r] = s * inv * inv;
                }
            }
        }
        __syncthreads();

        // ---- ballot-compacted routing: lane tests rows lane+32h ----
        unsigned masks[4];
        #pragma unroll
        for (int h = 0; h < 4; ++h) {
            int ri = lane + h * 32;
            int lb = slb[ri];
            masks[h] = __ballot_sync(0xffffffffu,
                                     (ri < nrows) && ((unsigned)(lb - base) < 4u));
        }
        #pragma unroll
        for (int h = 0; h < 4; ++h) {
            for (unsigned m = masks[h]; m; m &= m - 1) {
                int i = (__ffs(m) - 1) + h * 32;
                int k = slb[i] - base;                 // uniform per warp
                float  inv = siv[i];
                float  z2  = sz2[i];
                float4 xv  = ((const float4*)&sx[i * D])[lane];
                if (k == 0) {
                    a0.x = fmaf(xv.x, inv, a0.x); a0.y = fmaf(xv.y, inv, a0.y);
                    a0.z = fmaf(xv.z, inv, a0.z); a0.w = fmaf(xv.w, inv, a0.w);
                    c0 += 1.0f; q0 += z2;
                } else if (k == 1) {
                    a1.x = fmaf(xv.x, inv, a1.x); a1.y = fmaf(xv.y, inv, a1.y);
                    a1.z = fmaf(xv.z, inv, a1.z); a1.w = fmaf(xv.w, inv, a1.w);
                    c1 += 1.0f; q1 += z2;
                } else if (k == 2) {
                    a2.x = fmaf(xv.x, inv, a2.x); a2.y = fmaf(xv.y, inv, a2.y);
                    a2.z = fmaf(xv.z, inv, a2.z); a2.w = fmaf(xv.w, inv, a2.w);
                    c2 += 1.0f; q2 += z2;
                } else {
                    a3.x = fmaf(xv.x, inv, a3.x); a3.y = fmaf(xv.y, inv, a3.y);
                    a3.z = fmaf(xv.z, inv, a3.z); a3.w = fmaf(xv.w, inv, a3.w);
                    c3 += 1.0f; q3 += z2;
                }
            }
        }
        __syncthreads();
        parity ^= 1;
    }

    // ---- flush per-class accumulators (one-shot) ----
    const int dbase = lane * 4;
    atomicAdd(&g_sums[(base + 0) * D + dbase + 0], a0.x);
    atomicAdd(&g_sums[(base + 0) * D + dbase + 1], a0.y);
    atomicAdd(&g_sums[(base + 0) * D + dbase + 2], a0.z);
    atomicAdd(&g_sums[(base + 0) * D + dbase + 3], a0.w);
    atomicAdd(&g_sums[(base + 1) * D + dbase + 0], a1.x);
    atomicAdd(&g_sums[(base + 1) * D + dbase + 1], a1.y);
    atomicAdd(&g_sums[(base + 1) * D + dbase + 2], a1.z);
    atomicAdd(&g_sums[(base + 1) * D + dbase + 3], a1.w);
    atomicAdd(&g_sums[(base + 2) * D + dbase + 0], a2.x);
    atomicAdd(&g_sums[(base + 2) * D + dbase + 1], a2.y);
    atomicAdd(&g_sums[(base + 2) * D + dbase + 2], a2.z);
    atomicAdd(&g_sums[(base + 2) * D + dbase + 3], a2.w);
    atomicAdd(&g_sums[(base + 3) * D + dbase + 0], a3.x);
    atomicAdd(&g_sums[(base + 3) * D + dbase + 1], a3.y);
    atomicAdd(&g_sums[(base + 3) * D + dbase + 2], a3.z);
    atomicAdd(&g_sums[(base + 3) * D + dbase + 3], a3.w);
    if (lane == 0) {
        atomicAdd(&g_counts[base + 0], c0); atomicAdd(&g_z2[base + 0], q0);
        atomicAdd(&g_counts[base + 1], c1); atomicAdd(&g_z2[base + 1], q1);
        atomicAdd(&g_counts[base + 2], c2); atomicAdd(&g_z2[base + 2], q2);
        atomicAdd(&g_counts[base + 3], c3); atomicAdd(&g_z2[base + 3], q3);
    }

    // ---------------- CE phase (4-row ILP per warp) ----------------
    const int gw = blockIdx.x * (THREADS_MAIN / 32) + wid;
    const int nw = GRID_MAIN * (THREADS_MAIN / 32);
    float acc = 0.0f;

    const float2* lg2 = (const float2*)logits;
    for (int row = gw; row < N; row += 4 * nw) {
        float2 v[4]; int lbl[4]; bool has[4];
        #pragma unroll
        for (int j = 0; j < 4; ++j) {
            int r = row + j * nw;
            has[j] = r < N;
            v[j] = has[j] ? lg2[(size_t)r * (C / 2) + lane] : make_float2(0.f, 0.f);
            lbl[j] = has[j] ? (int)lab_w[lbl64 ? 2 * r : r] : 0;
        }
        float m[4], e[4];
        #pragma unroll
        for (int j = 0; j < 4; ++j) m[j] = fmaxf(v[j].x, v[j].y);
        #pragma unroll
        for (int o = 16; o; o >>= 1) {
            #pragma unroll
            for (int j = 0; j < 4; ++j)
                m[j] = fmaxf(m[j], __shfl_xor_sync(0xffffffffu, m[j], o));
        }
        #pragma unroll
        for (int j = 0; j < 4; ++j)
            e[j] = __expf(v[j].x - m[j]) + __expf(v[j].y - m[j]);
        #pragma unroll
        for (int o = 16; o; o >>= 1) {
            #pragma unroll
            for (int j = 0; j < 4; ++j)
                e[j] += __shfl_xor_sync(0xffffffffu, e[j], o);
        }
        #pragma unroll
        for (int j = 0; j < 4; ++j) {
            float pick = (lbl[j] & 1) ? v[j].y : v[j].x;
            float gv = __shfl_sync(0xffffffffu, pick, lbl[j] >> 1);
            if (lane == 0 && has[j]) acc += (m[j] + __logf(e[j])) - gv;
        }
    }

    __syncthreads();
    if (lane == 0) s_red[wid] = acc;
    __syncthreads();
    if (tid == 0) {
        float s = 0.0f;
        #pragma unroll
        for (int i = 0; i < THREADS_MAIN / 32; ++i) s += s_red[i];
        atomicAdd(&g_ce, s);
    }
}

// ---------------------------------------------------------
// finalize: combine, write scalar, then RE-ZERO scratch for the next call.
// ---------------------------------------------------------
__global__ __launch_bounds__(256)
void finalize_kernel(float* __restrict__ out, int N) {
    __shared__ float s_pc[C];
    __shared__ float s_v[C];
    int wid = threadIdx.x >> 5, lane = threadIdx.x & 31;
    for (int c = wid; c < C; c += 8) {
        float4 v = ((const float4*)(g_sums + c * D))[lane];
        float dot = v.x*v.x + v.y*v.y + v.z*v.z + v.w*v.w;
        #pragma unroll
        for (int o = 16; o; o >>= 1) dot += __shfl_xor_sync(0xffffffffu, dot, o);
        if (lane == 0) {
            float cnt  = g_counts[c];
            float safe = fmaxf(cnt, 1.0f);
            float musq = dot / (safe * safe);
            float ssd  = g_z2[c] - cnt * musq;
            bool valid = (cnt > 1.0f);
            s_pc[c] = valid ? (ssd / safe) : 0.0f;
            s_v[c]  = valid ? 1.0f : 0.0f;
        }
    }
    __syncthreads();
    if (threadIdx.x == 0) {
        float sp = 0.0f, nv = 0.0f;
        #pragma unroll
        for (int c = 0; c < C; ++c) { sp += s_pc[c]; nv += s_v[c]; }
        float proto = sp / fmaxf(nv, 1.0f);
        float ce    = g_ce / (float)N;
        out[0] = (1.0f - LAMBDA_PROTO) * ce + LAMBDA_PROTO * proto;
    }
    // re-zero scratch for the next invocation (globals start zeroed at load)
    for (int i = threadIdx.x; i < C * D; i += blockDim.x) g_sums[i] = 0.0f;
    if (threadIdx.x < C) { g_counts[threadIdx.x] = 0.0f; g_z2[threadIdx.x] = 0.0f; }
    if (threadIdx.x == 0) g_ce = 0.0f;
}

// ---------------------------------------------------------
extern "C" void kernel_launch(void* const* d_in, const int* in_sizes, int n_in,
                              void* d_out, int out_size) {
    const float* emb          = (const float*)d_in[0];
    const float* logits       = (const float*)d_in[1];
    const unsigned int* lab_w = (const unsigned int*)d_in[2];
    int N = in_sizes[2];

    cudaFuncSetAttribute(fused_kernel,
                         cudaFuncAttributeMaxDynamicSharedMemorySize, SMEM_BYTES);

    fused_kernel<<<GRID_MAIN, THREADS_MAIN, SMEM_BYTES>>>(emb, logits, lab_w, N);
    finalize_kernel<<<1, 256>>>((float*)d_out, N);
}

// round 5
// speedup vs baseline: 1.1920x; 1.1920x over previous
#include <cuda_runtime.h>
#include <cuda_bf16.h>
#include <math.h>

#define D 128
#define C 64
#define ROWS_PER_TILE 64
#define THREADS_MAIN 512   // 16 warps, each owns 4 classes
#define GRID_MAIN 296      // 2 blocks/SM: exactly one wave on 148 SMs
#define LAMBDA_PROTO 0.5f

// -------- device scratch (zero at module load; last block re-zeroes) --------
__device__ float g_sums[C * D];
__device__ float g_counts[C];
__device__ float g_z2[C];
__device__ float g_ce;
__device__ unsigned int g_done;

// smem (bytes): s_x 2*64*128f=65536 ; s_inv 2*64f=512 ; s_z2 2*64f=512 ;
//               s_lbl 2*64i=512 ; s_red 64f=256
#define SMEM_BYTES (65536 + 512 + 512 + 512 + 256)

// ---------------------------------------------------------
__device__ __forceinline__ void stage_tile_async(
    const float* __restrict__ emb, const unsigned int* __restrict__ lab_w,
    int lbl64, int row0, int nrows,
    float* s_x_buf, int* s_lbl_buf, int tid)
{
    const float4* g = (const float4*)(emb + (size_t)row0 * D);
    unsigned int dstx = (unsigned int)__cvta_generic_to_shared(s_x_buf);
    if (nrows == ROWS_PER_TILE) {
        #pragma unroll
        for (int k = 0; k < ROWS_PER_TILE * (D / 4) / THREADS_MAIN; ++k) {
            int i = tid + k * THREADS_MAIN;
            asm volatile("cp.async.cg.shared.global [%0], [%1], 16;\n"
                         :: "r"(dstx + i * 16), "l"(g + i));
        }
    } else {
        int nf4 = nrows * (D / 4);
        for (int i = tid; i < nf4; i += THREADS_MAIN) {
            asm volatile("cp.async.cg.shared.global [%0], [%1], 16;\n"
                         :: "r"(dstx + i * 16), "l"(g + i));
        }
    }
    if (tid < nrows) {
        const unsigned int* src = lab_w + (lbl64 ? 2 * (row0 + tid) : (row0 + tid));
        unsigned int dstl = (unsigned int)__cvta_generic_to_shared(s_lbl_buf + tid);
        asm volatile("cp.async.ca.shared.global [%0], [%1], 4;\n"
                     :: "r"(dstl), "l"(src));
    }
}

// ---------------------------------------------------------
__global__ __launch_bounds__(THREADS_MAIN, 2)
void fused_kernel(const float* __restrict__ emb,
                  const float* __restrict__ logits,
                  const unsigned int* __restrict__ lab_w, int N,
                  float* __restrict__ out)
{
    extern __shared__ float smem[];
    float* s_x   = smem;                                  // [2][64*128]
    float* s_inv = smem + 2 * ROWS_PER_TILE * D;          // [2][64]
    float* s_z2  = s_inv + 2 * ROWS_PER_TILE;             // [2][64]
    int*   s_lbl = (int*)(s_z2 + 2 * ROWS_PER_TILE);      // [2][64]
    float* s_red = (float*)(s_lbl + 2 * ROWS_PER_TILE);   // [64]

    const int tid  = threadIdx.x;
    const int wid  = tid >> 5;
    const int lane = tid & 31;
    const int base = wid * 4;          // warp owns classes [base, base+4)

    // --- per-warp label dtype detection (no sync, no extra kernel) ---
    unsigned probe = lab_w[2 * lane + 1];
    int lbl64 = (__ballot_sync(0xffffffffu, probe != 0u) == 0u);

    float4 a0 = {0,0,0,0}, a1 = a0, a2 = a0, a3 = a0;
    float  c0 = 0, c1 = 0, c2 = 0, c3 = 0;
    float  q0 = 0, q1 = 0, q2 = 0, q3 = 0;

    const int ntiles = (N + ROWS_PER_TILE - 1) / ROWS_PER_TILE;

    int tile = blockIdx.x;
    if (tile < ntiles) {
        int row0 = tile * ROWS_PER_TILE;
        stage_tile_async(emb, lab_w, lbl64, row0,
                         min(ROWS_PER_TILE, N - row0), s_x, s_lbl, tid);
    }
    asm volatile("cp.async.commit_group;\n" ::: "memory");

    int parity = 0;
    for (; tile < ntiles; tile += GRID_MAIN) {
        int nt = tile + GRID_MAIN;
        if (nt < ntiles) {
            int nrow0 = nt * ROWS_PER_TILE;
            stage_tile_async(emb, lab_w, lbl64, nrow0,
                             min(ROWS_PER_TILE, N - nrow0),
                             s_x + (parity ^ 1) * ROWS_PER_TILE * D,
                             s_lbl + (parity ^ 1) * ROWS_PER_TILE, tid);
        }
        asm volatile("cp.async.commit_group;\n" ::: "memory");
        asm volatile("cp.async.wait_group 1;\n" ::: "memory");
        __syncthreads();

        const int nrows = min(ROWS_PER_TILE, N - tile * ROWS_PER_TILE);
        float* sx  = s_x   + parity * ROWS_PER_TILE * D;
        float* siv = s_inv + parity * ROWS_PER_TILE;
        float* sz2 = s_z2  + parity * ROWS_PER_TILE;
        int*   slb = s_lbl + parity * ROWS_PER_TILE;

        // ---- parallel norm phase: 8 threads/row, 64 rows -> all 512 threads ----
        {
            int r = tid >> 3;          // row 0..63
            int q = tid & 7;           // eighth
            if (r < nrows) {
                const float4* rp = (const float4*)&sx[r * D] + q * 4;
                float s = 0.0f;
                #pragma unroll
                for (int i = 0; i < 4; ++i) {
                    float4 v = rp[i];
                    s += v.x*v.x + v.y*v.y + v.z*v.z + v.w*v.w;
                }
                s += __shfl_xor_sync(0xffffffffu, s, 1);
                s += __shfl_xor_sync(0xffffffffu, s, 2);
                s += __shfl_xor_sync(0xffffffffu, s, 4);
                if (q == 0) {
                    float inv = rsqrtf(fmaxf(s, 1e-24f));  // == 1/max(||x||,1e-12)
                    siv[r] = inv;
                    sz2[r] = s * inv * inv;
                }
            }
        }
        __syncthreads();

        // ---- ballot-compacted routing ----
        unsigned m0, m1;
        {
            int lb0 = slb[lane];
            int lb1 = slb[lane + 32];
            m0 = __ballot_sync(0xffffffffu,
                               (lane < nrows) && ((unsigned)(lb0 - base) < 4u));
            m1 = __ballot_sync(0xffffffffu,
                               (lane + 32 < nrows) && ((unsigned)(lb1 - base) < 4u));
        }
        #pragma unroll 1
        for (unsigned mm = m0, half = 0; ; mm = m1, half = 32) {
            for (unsigned m = mm; m; m &= m - 1) {
                int i = (__ffs(m) - 1) + half;
                int k = slb[i] - base;                 // uniform per warp
                float  inv = siv[i];
                float  z2  = sz2[i];
                float4 xv  = ((const float4*)&sx[i * D])[lane];
                if (k == 0) {
                    a0.x = fmaf(xv.x, inv, a0.x); a0.y = fmaf(xv.y, inv, a0.y);
                    a0.z = fmaf(xv.z, inv, a0.z); a0.w = fmaf(xv.w, inv, a0.w);
                    c0 += 1.0f; q0 += z2;
                } else if (k == 1) {
                    a1.x = fmaf(xv.x, inv, a1.x); a1.y = fmaf(xv.y, inv, a1.y);
                    a1.z = fmaf(xv.z, inv, a1.z); a1.w = fmaf(xv.w, inv, a1.w);
                    c1 += 1.0f; q1 += z2;
                } else if (k == 2) {
                    a2.x = fmaf(xv.x, inv, a2.x); a2.y = fmaf(xv.y, inv, a2.y);
                    a2.z = fmaf(xv.z, inv, a2.z); a2.w = fmaf(xv.w, inv, a2.w);
                    c2 += 1.0f; q2 += z2;
                } else {
                    a3.x = fmaf(xv.x, inv, a3.x); a3.y = fmaf(xv.y, inv, a3.y);
                    a3.z = fmaf(xv.z, inv, a3.z); a3.w = fmaf(xv.w, inv, a3.w);
                    c3 += 1.0f; q3 += z2;
                }
            }
            if (half) break;
        }
        __syncthreads();
        parity ^= 1;
    }

    // ---- flush per-class accumulators (one-shot) ----
    const int dbase = lane * 4;
    atomicAdd(&g_sums[(base + 0) * D + dbase + 0], a0.x);
    atomicAdd(&g_sums[(base + 0) * D + dbase + 1], a0.y);
    atomicAdd(&g_sums[(base + 0) * D + dbase + 2], a0.z);
    atomicAdd(&g_sums[(base + 0) * D + dbase + 3], a0.w);
    atomicAdd(&g_sums[(base + 1) * D + dbase + 0], a1.x);
    atomicAdd(&g_sums[(base + 1) * D + dbase + 1], a1.y);
    atomicAdd(&g_sums[(base + 1) * D + dbase + 2], a1.z);
    atomicAdd(&g_sums[(base + 1) * D + dbase + 3], a1.w);
    atomicAdd(&g_sums[(base + 2) * D + dbase + 0], a2.x);
    atomicAdd(&g_sums[(base + 2) * D + dbase + 1], a2.y);
    atomicAdd(&g_sums[(base + 2) * D + dbase + 2], a2.z);
    atomicAdd(&g_sums[(base + 2) * D + dbase + 3], a2.w);
    atomicAdd(&g_sums[(base + 3) * D + dbase + 0], a3.x);
    atomicAdd(&g_sums[(base + 3) * D + dbase + 1], a3.y);
    atomicAdd(&g_sums[(base + 3) * D + dbase + 2], a3.z);
    atomicAdd(&g_sums[(base + 3) * D + dbase + 3], a3.w);
    if (lane == 0) {
        atomicAdd(&g_counts[base + 0], c0); atomicAdd(&g_z2[base + 0], q0);
        atomicAdd(&g_counts[base + 1], c1); atomicAdd(&g_z2[base + 1], q1);
        atomicAdd(&g_counts[base + 2], c2); atomicAdd(&g_z2[base + 2], q2);
        atomicAdd(&g_counts[base + 3], c3); atomicAdd(&g_z2[base + 3], q3);
    }

    // ---------------- CE phase (4-row ILP per warp) ----------------
    const int gw = blockIdx.x * (THREADS_MAIN / 32) + wid;
    const int nw = GRID_MAIN * (THREADS_MAIN / 32);
    float acc = 0.0f;

    const float2* lg2 = (const float2*)logits;
    for (int row = gw; row < N; row += 4 * nw) {
        float2 v[4]; int lbl[4]; bool has[4];
        #pragma unroll
        for (int j = 0; j < 4; ++j) {
            int r = row + j * nw;
            has[j] = r < N;
            v[j] = has[j] ? lg2[(size_t)r * (C / 2) + lane] : make_float2(0.f, 0.f);
            lbl[j] = has[j] ? (int)lab_w[lbl64 ? 2 * r : r] : 0;
        }
        float m[4], e[4];
        #pragma unroll
        for (int j = 0; j < 4; ++j) m[j] = fmaxf(v[j].x, v[j].y);
        #pragma unroll
        for (int o = 16; o; o >>= 1) {
            #pragma unroll
            for (int j = 0; j < 4; ++j)
                m[j] = fmaxf(m[j], __shfl_xor_sync(0xffffffffu, m[j], o));
        }
        #pragma unroll
        for (int j = 0; j < 4; ++j)
            e[j] = __expf(v[j].x - m[j]) + __expf(v[j].y - m[j]);
        #pragma unroll
        for (int o = 16; o; o >>= 1) {
            #pragma unroll
            for (int j = 0; j < 4; ++j)
                e[j] += __shfl_xor_sync(0xffffffffu, e[j], o);
        }
        #pragma unroll
        for (int j = 0; j < 4; ++j) {
            float pick = (lbl[j] & 1) ? v[j].y : v[j].x;
            float gv = __shfl_sync(0xffffffffu, pick, lbl[j] >> 1);
            if (lane == 0 && has[j]) acc += (m[j] + __logf(e[j])) - gv;
        }
    }

    __syncthreads();
    if (lane == 0) s_red[wid] = acc;
    __syncthreads();

    // block's CE contribution + completion mark
    __shared__ unsigned int s_rank;
    if (tid == 0) {
        float s = 0.0f;
        #pragma unroll
        for (int i = 0; i < THREADS_MAIN / 32; ++i) s += s_red[i];
        atomicAdd(&g_ce, s);
        __threadfence();
        s_rank = atomicAdd(&g_done, 1u);
    }
    __syncthreads();

    // ---------------- last block: finalize + re-zero scratch ----------------
    if (s_rank == GRID_MAIN - 1) {
        __threadfence();  // acquire: see all blocks' atomics

        // warp w -> classes base..base+3 ; reuse s_red as s_pc/s_v
        float* s_pc = s_red;             // [16] -> need 64: use s_x area
        float* pcv  = s_x;               // plenty of smem free now
        #pragma unroll
        for (int cc = 0; cc < 4; ++cc) {
            int c = base + cc;
            float4 v = ((const float4*)(g_sums + c * D))[lane];
            float dot = v.x*v.x + v.y*v.y + v.z*v.z + v.w*v.w;
            #pragma unroll
            for (int o = 16; o; o >>= 1) dot += __shfl_xor_sync(0xffffffffu, dot, o);
            if (lane == 0) {
                float cnt  = g_counts[c];
                float safe = fmaxf(cnt, 1.0f);
                float ssd  = g_z2[c] - dot / safe;
                bool valid = (cnt > 1.0f);
                pcv[c]      = valid ? (ssd / safe) : 0.0f;
                pcv[C + c]  = valid ? 1.0f : 0.0f;
            }
        }
        __syncthreads();
        if (tid == 0) {
            float sp = 0.0f, nv = 0.0f;
            #pragma unroll
            for (int c = 0; c < C; ++c) { sp += pcv[c]; nv += pcv[C + c]; }
            float proto = sp / fmaxf(nv, 1.0f);
            float ce    = g_ce / (float)N;
            out[0] = (1.0f - LAMBDA_PROTO) * ce + LAMBDA_PROTO * proto;
        }
        (void)s_pc;

        // re-zero scratch for next graph replay
        for (int i = tid; i < C * D; i += THREADS_MAIN) g_sums[i] = 0.0f;
        if (tid < C) { g_counts[tid] = 0.0f; g_z2[tid] = 0.0f; }
        if (tid == 0) { g_ce = 0.0f; __threadfence(); g_done = 0u; }
    }
}

// ---------------------------------------------------------
extern "C" void kernel_launch(void* const* d_in, const int* in_sizes, int n_in,
                              void* d_out, int out_size) {
    const float* emb          = (const float*)d_in[0];
    const float* logits       = (const float*)d_in[1];
    const unsigned int* lab_w = (const unsigned int*)d_in[2];
    int N = in_sizes[2];

    cudaFuncSetAttribute(fused_kernel,
                         cudaFuncAttributeMaxDynamicSharedMemorySize, SMEM_BYTES);

    fused_kernel<<<GRID_MAIN, THREADS_MAIN, SMEM_BYTES>>>(
        emb, logits, lab_w, N, (float*)d_out);
}

// round 6
// speedup vs baseline: 1.4049x; 1.1786x over previous
#include <cuda_runtime.h>
#include <cuda_bf16.h>
#include <math.h>

#define D 128
#define C 64
#define ROWS_PER_TILE 128
#define THREADS_MAIN 512   // 16 warps, each owns 4 classes
#define GRID_MAIN 296      // 2 blocks/SM: exactly one wave on 148 SMs
#define LAMBDA_PROTO 0.5f

// -------- device scratch (zero at module load; last block re-zeroes) --------
__device__ float g_sums[C * D];
__device__ float g_counts[C];
__device__ float g_z2[C];
__device__ float g_ce;
__device__ unsigned int g_done;

// ---------------------------------------------------------
// accumulate one normalized row into the right class slot
// ---------------------------------------------------------
#define ACC_ROW(k, xv, inv, z2)                                            \
    do {                                                                   \
        if ((k) == 0) {                                                    \
            a0.x = fmaf((xv).x, (inv), a0.x); a0.y = fmaf((xv).y, (inv), a0.y); \
            a0.z = fmaf((xv).z, (inv), a0.z); a0.w = fmaf((xv).w, (inv), a0.w); \
            c0 += 1.0f; q0 += (z2);                                        \
        } else if ((k) == 1) {                                             \
            a1.x = fmaf((xv).x, (inv), a1.x); a1.y = fmaf((xv).y, (inv), a1.y); \
            a1.z = fmaf((xv).z, (inv), a1.z); a1.w = fmaf((xv).w, (inv), a1.w); \
            c1 += 1.0f; q1 += (z2);                                        \
        } else if ((k) == 2) {                                             \
            a2.x = fmaf((xv).x, (inv), a2.x); a2.y = fmaf((xv).y, (inv), a2.y); \
            a2.z = fmaf((xv).z, (inv), a2.z); a2.w = fmaf((xv).w, (inv), a2.w); \
            c2 += 1.0f; q2 += (z2);                                        \
        } else {                                                           \
            a3.x = fmaf((xv).x, (inv), a3.x); a3.y = fmaf((xv).y, (inv), a3.y); \
            a3.z = fmaf((xv).z, (inv), a3.z); a3.w = fmaf((xv).w, (inv), a3.w); \
            c3 += 1.0f; q3 += (z2);                                        \
        }                                                                  \
    } while (0)

// ---------------------------------------------------------
__global__ __launch_bounds__(THREADS_MAIN, 2)
void fused_kernel(const float* __restrict__ emb,
                  const float* __restrict__ logits,
                  const unsigned int* __restrict__ lab_w, int N,
                  float* __restrict__ out)
{
    __shared__ float s_red[16];
    __shared__ float s_pc[2 * C];
    __shared__ unsigned int s_rank;

    const int tid  = threadIdx.x;
    const int wid  = tid >> 5;
    const int lane = tid & 31;
    const int base = wid * 4;          // warp owns classes [base, base+4)

    // --- per-warp label dtype detection ---
    unsigned probe = lab_w[2 * lane + 1];
    const int lbl64 = (__ballot_sync(0xffffffffu, probe != 0u) == 0u);

    float4 a0 = {0,0,0,0}, a1 = a0, a2 = a0, a3 = a0;
    float  c0 = 0, c1 = 0, c2 = 0, c3 = 0;
    float  q0 = 0, q1 = 0, q2 = 0, q3 = 0;

    const float4* emb4 = (const float4*)emb;
    const int ntiles = (N + ROWS_PER_TILE - 1) / ROWS_PER_TILE;

    // =========== proto phase: zero-SMEM direct-gather routing ===========
    for (int tile = blockIdx.x; tile < ntiles; tile += GRID_MAIN) {
        const int row0 = tile * ROWS_PER_TILE;

        // lane reads labels for rows row0 + lane + 32h, h = 0..3
        int lb[4];
        unsigned mask[4];
        #pragma unroll
        for (int h = 0; h < 4; ++h) {
            int r = row0 + lane + 32 * h;
            int v = (r < N) ? (int)lab_w[lbl64 ? 2 * r : r] : -1;
            lb[h] = v;
            mask[h] = __ballot_sync(0xffffffffu, (unsigned)(v - base) < 4u);
        }

        // process matched rows two-at-a-time for MLP
        #pragma unroll
        for (int h = 0; h < 4; ++h) {
            unsigned m = mask[h];
            while (m) {
                int j0 = __ffs(m) - 1; m &= m - 1;
                bool two = (m != 0u);
                int j1 = two ? (__ffs(m) - 1) : j0;
                if (two) m &= m - 1;

                int kA = __shfl_sync(0xffffffffu, lb[h], j0) - base;
                int kB = __shfl_sync(0xffffffffu, lb[h], j1) - base;
                size_t rA = (size_t)(row0 + 32 * h + j0);
                size_t rB = (size_t)(row0 + 32 * h + j1);

                float4 xA = emb4[rA * (D / 4) + lane];
                float4 xB = emb4[rB * (D / 4) + lane];

                float sA = xA.x*xA.x + xA.y*xA.y + xA.z*xA.z + xA.w*xA.w;
                float sB = xB.x*xB.x + xB.y*xB.y + xB.z*xB.z + xB.w*xB.w;
                #pragma unroll
                for (int o = 16; o; o >>= 1) {
                    sA += __shfl_xor_sync(0xffffffffu, sA, o);
                    sB += __shfl_xor_sync(0xffffffffu, sB, o);
                }
                float invA = rsqrtf(fmaxf(sA, 1e-24f));  // == 1/max(||x||,1e-12)
                float invB = rsqrtf(fmaxf(sB, 1e-24f));
                float z2A = sA * invA * invA;
                float z2B = sB * invB * invB;

                ACC_ROW(kA, xA, invA, z2A);
                if (two) ACC_ROW(kB, xB, invB, z2B);
            }
        }
    }

    // ---- flush per-class accumulators (one-shot) ----
    const int dbase = lane * 4;
    atomicAdd(&g_sums[(base + 0) * D + dbase + 0], a0.x);
    atomicAdd(&g_sums[(base + 0) * D + dbase + 1], a0.y);
    atomicAdd(&g_sums[(base + 0) * D + dbase + 2], a0.z);
    atomicAdd(&g_sums[(base + 0) * D + dbase + 3], a0.w);
    atomicAdd(&g_sums[(base + 1) * D + dbase + 0], a1.x);
    atomicAdd(&g_sums[(base + 1) * D + dbase + 1], a1.y);
    atomicAdd(&g_sums[(base + 1) * D + dbase + 2], a1.z);
    atomicAdd(&g_sums[(base + 1) * D + dbase + 3], a1.w);
    atomicAdd(&g_sums[(base + 2) * D + dbase + 0], a2.x);
    atomicAdd(&g_sums[(base + 2) * D + dbase + 1], a2.y);
    atomicAdd(&g_sums[(base + 2) * D + dbase + 2], a2.z);
    atomicAdd(&g_sums[(base + 2) * D + dbase + 3], a2.w);
    atomicAdd(&g_sums[(base + 3) * D + dbase + 0], a3.x);
    atomicAdd(&g_sums[(base + 3) * D + dbase + 1], a3.y);
    atomicAdd(&g_sums[(base + 3) * D + dbase + 2], a3.z);
    atomicAdd(&g_sums[(base + 3) * D + dbase + 3], a3.w);
    if (lane == 0) {
        atomicAdd(&g_counts[base + 0], c0); atomicAdd(&g_z2[base + 0], q0);
        atomicAdd(&g_counts[base + 1], c1); atomicAdd(&g_z2[base + 1], q1);
        atomicAdd(&g_counts[base + 2], c2); atomicAdd(&g_z2[base + 2], q2);
        atomicAdd(&g_counts[base + 3], c3); atomicAdd(&g_z2[base + 3], q3);
    }

    // =========== CE phase (4-row ILP per warp) ===========
    const int gw = blockIdx.x * (THREADS_MAIN / 32) + wid;
    const int nw = GRID_MAIN * (THREADS_MAIN / 32);
    float acc = 0.0f;

    const float2* lg2 = (const float2*)logits;
    for (int row = gw; row < N; row += 4 * nw) {
        float2 v[4]; int lbl[4]; bool has[4];
        #pragma unroll
        for (int j = 0; j < 4; ++j) {
            int r = row + j * nw;
            has[j] = r < N;
            v[j] = has[j] ? lg2[(size_t)r * (C / 2) + lane] : make_float2(0.f, 0.f);
            lbl[j] = has[j] ? (int)lab_w[lbl64 ? 2 * r : r] : 0;
        }
        float m[4], e[4];
        #pragma unroll
        for (int j = 0; j < 4; ++j) m[j] = fmaxf(v[j].x, v[j].y);
        #pragma unroll
        for (int o = 16; o; o >>= 1) {
            #pragma unroll
            for (int j = 0; j < 4; ++j)
                m[j] = fmaxf(m[j], __shfl_xor_sync(0xffffffffu, m[j], o));
        }
        #pragma unroll
        for (int j = 0; j < 4; ++j)
            e[j] = __expf(v[j].x - m[j]) + __expf(v[j].y - m[j]);
        #pragma unroll
        for (int o = 16; o; o >>= 1) {
            #pragma unroll
            for (int j = 0; j < 4; ++j)
                e[j] += __shfl_xor_sync(0xffffffffu, e[j], o);
        }
        #pragma unroll
        for (int j = 0; j < 4; ++j) {
            float pick = (lbl[j] & 1) ? v[j].y : v[j].x;
            float gv = __shfl_sync(0xffffffffu, pick, lbl[j] >> 1);
            if (lane == 0 && has[j]) acc += (m[j] + __logf(e[j])) - gv;
        }
    }

    if (lane == 0) s_red[wid] = acc;
    __syncthreads();

    if (tid == 0) {
        float s = 0.0f;
        #pragma unroll
        for (int i = 0; i < THREADS_MAIN / 32; ++i) s += s_red[i];
        atomicAdd(&g_ce, s);
        __threadfence();
        s_rank = atomicAdd(&g_done, 1u);
    }
    __syncthreads();

    // =========== last block: finalize + re-zero scratch ===========
    if (s_rank == GRID_MAIN - 1) {
        __threadfence();  // see all blocks' atomics

        #pragma unroll
        for (int cc = 0; cc < 4; ++cc) {
            int c = base + cc;
            float4 v = ((const float4*)(g_sums + c * D))[lane];
            float dot = v.x*v.x + v.y*v.y + v.z*v.z + v.w*v.w;
            #pragma unroll
            for (int o = 16; o; o >>= 1) dot += __shfl_xor_sync(0xffffffffu, dot, o);
            if (lane == 0) {
                float cnt  = g_counts[c];
                float safe = fmaxf(cnt, 1.0f);
                float ssd  = g_z2[c] - dot / safe;
                bool valid = (cnt > 1.0f);
                s_pc[c]     = valid ? (ssd / safe) : 0.0f;
                s_pc[C + c] = valid ? 1.0f : 0.0f;
            }
        }
        __syncthreads();
        if (tid == 0) {
            float sp = 0.0f, nv = 0.0f;
            #pragma unroll
            for (int c = 0; c < C; ++c) { sp += s_pc[c]; nv += s_pc[C + c]; }
            float proto = sp / fmaxf(nv, 1.0f);
            float ce    = g_ce / (float)N;
            out[0] = (1.0f - LAMBDA_PROTO) * ce + LAMBDA_PROTO * proto;
        }

        // re-zero scratch for next graph replay
        for (int i = tid; i < C * D; i += THREADS_MAIN) g_sums[i] = 0.0f;
        if (tid < C) { g_counts[tid] = 0.0f; g_z2[tid] = 0.0f; }
        if (tid == 0) { g_ce = 0.0f; __threadfence(); g_done = 0u; }
    }
}

// ---------------------------------------------------------
extern "C" void kernel_launch(void* const* d_in, const int* in_sizes, int n_in,
                              void* d_out, int out_size) {
    const float* emb          = (const float*)d_in[0];
    const float* logits       = (const float*)d_in[1];
    const unsigned int* lab_w = (const unsigned int*)d_in[2];
    int N = in_sizes[2];

    fused_kernel<<<GRID_MAIN, THREADS_MAIN>>>(emb, logits, lab_w, N, (float*)d_out);
}

// round 8
// speedup vs baseline: 1.4808x; 1.0540x over previous
#include <cuda_runtime.h>
#include <cuda_bf16.h>
#include <math.h>

#define D 128
#define C 64
#define ROWS_PER_TILE 128
#define THREADS_MAIN 512   // 16 warps, each owns 4 classes
#define GRID_MAIN 296      // 2 blocks/SM: exactly one wave on 148 SMs
#define LAMBDA_PROTO 0.5f

// -------- device scratch (zero at module load; last block re-zeroes) --------
__device__ float g_sums[C * D];
__device__ float g_counts[C];
__device__ float g_z2[C];
__device__ float g_ce;
__device__ unsigned int g_done;

#define ACC_ROW(k, xv, inv, z2)                                            \
    do {                                                                   \
        if ((k) == 0) {                                                    \
            a0.x = fmaf((xv).x, (inv), a0.x); a0.y = fmaf((xv).y, (inv), a0.y); \
            a0.z = fmaf((xv).z, (inv), a0.z); a0.w = fmaf((xv).w, (inv), a0.w); \
            c0 += 1.0f; q0 += (z2);                                        \
        } else if ((k) == 1) {                                             \
            a1.x = fmaf((xv).x, (inv), a1.x); a1.y = fmaf((xv).y, (inv), a1.y); \
            a1.z = fmaf((xv).z, (inv), a1.z); a1.w = fmaf((xv).w, (inv), a1.w); \
            c1 += 1.0f; q1 += (z2);                                        \
        } else if ((k) == 2) {                                             \
            a2.x = fmaf((xv).x, (inv), a2.x); a2.y = fmaf((xv).y, (inv), a2.y); \
            a2.z = fmaf((xv).z, (inv), a2.z); a2.w = fmaf((xv).w, (inv), a2.w); \
            c2 += 1.0f; q2 += (z2);                                        \
        } else {                                                           \
            a3.x = fmaf((xv).x, (inv), a3.x); a3.y = fmaf((xv).y, (inv), a3.y); \
            a3.z = fmaf((xv).z, (inv), a3.z); a3.w = fmaf((xv).w, (inv), a3.w); \
            c3 += 1.0f; q3 += (z2);                                        \
        }                                                                  \
    } while (0)

// ---------------------------------------------------------
__global__ __launch_bounds__(THREADS_MAIN, 2)
void fused_kernel(const float* __restrict__ emb,
                  const float* __restrict__ logits,
                  const unsigned int* __restrict__ lab_w, int N,
                  float* __restrict__ out)
{
    __shared__ float s_red[16];
    __shared__ float s_pc[2 * C];
    __shared__ unsigned int s_rank;

    const int tid  = threadIdx.x;
    const int wid  = tid >> 5;
    const int lane = tid & 31;
    const int base = wid * 4;          // warp owns classes [base, base+4)

    // --- per-warp label dtype detection ---
    unsigned probe = lab_w[2 * lane + 1];
    const int lbl64 = (__ballot_sync(0xffffffffu, probe != 0u) == 0u);

    float4 a0 = {0,0,0,0}, a1 = a0, a2 = a0, a3 = a0;
    float  c0 = 0, c1 = 0, c2 = 0, c3 = 0;
    float  q0 = 0, q1 = 0, q2 = 0, q3 = 0;
    float  ce_acc = 0.0f;

    const float4*  emb4 = (const float4*)emb;
    const float2*  lg2  = (const float2*)logits;
    const int ntiles = (N + ROWS_PER_TILE - 1) / ROWS_PER_TILE;

    // =========== single pass: proto routing + CE per tile ===========
    for (int tile = blockIdx.x; tile < ntiles; tile += GRID_MAIN) {
        const int row0 = tile * ROWS_PER_TILE;

        // ---- proto: ballot ownership over the tile's 128 rows ----
        unsigned long long m128[2];
        {
            unsigned b[4];
            #pragma unroll
            for (int h = 0; h < 4; ++h) {
                int r = row0 + lane + 32 * h;
                int v = (r < N) ? (int)lab_w[lbl64 ? 2 * r : r] : -1;
                b[h] = __ballot_sync(0xffffffffu, (unsigned)(v - base) < 4u);
            }
            m128[0] = (unsigned long long)b[0] | ((unsigned long long)b[1] << 32);
            m128[1] = (unsigned long long)b[2] | ((unsigned long long)b[3] << 32);
        }

        // ---- process matched rows four-at-a-time (4 independent chains) ----
        #pragma unroll
        for (int part = 0; part < 2; ++part) {
            unsigned long long m = m128[part];
            const int pbase = row0 + part * 64;
            while (m) {
                int nb = 0;
                int r[4];
                #pragma unroll
                for (int j = 0; j < 4; ++j) {
                    if (m) {
                        r[j] = pbase + (int)(__ffsll((long long)m) - 1);
                        m &= m - 1;
                        nb = j + 1;
                    } else {
                        r[j] = r[0];   // duplicate, masked out below
                    }
                }
                int kk[4];
                float4 x[4];
                #pragma unroll
                for (int j = 0; j < 4; ++j) {
                    kk[j] = (int)lab_w[lbl64 ? 2 * r[j] : r[j]] - base;  // bcast
                    x[j]  = emb4[(size_t)r[j] * (D / 4) + lane];
                }
                float s[4];
                #pragma unroll
                for (int j = 0; j < 4; ++j)
                    s[j] = x[j].x*x[j].x + x[j].y*x[j].y + x[j].z*x[j].z + x[j].w*x[j].w;
                #pragma unroll
                for (int o = 16; o; o >>= 1) {
                    #pragma unroll
                    for (int j = 0; j < 4; ++j)
                        s[j] += __shfl_xor_sync(0xffffffffu, s[j], o);
                }
                #pragma unroll
                for (int j = 0; j < 4; ++j) {
                    if (j < nb) {
                        float inv = rsqrtf(fmaxf(s[j], 1e-24f)); // ==1/max(||x||,1e-12)
                        float z2  = s[j] * inv * inv;
                        ACC_ROW(kk[j], x[j], inv, z2);
                    }
                }
            }
        }

        // ---- CE: this warp handles 8 rows of the tile (2 x 4-ILP) ----
        #pragma unroll
        for (int u = 0; u < 2; ++u) {
            const int rbase = row0 + wid * 8 + u * 4;
            float2 v[4]; int lbl[4]; bool has[4];
            #pragma unroll
            for (int j = 0; j < 4; ++j) {
                int rr = rbase + j;
                has[j] = rr < N;
                v[j] = has[j] ? lg2[(size_t)rr * (C / 2) + lane]
                              : make_float2(0.f, 0.f);
                lbl[j] = has[j] ? (int)lab_w[lbl64 ? 2 * rr : rr] : 0;
            }
            float mx[4], e[4];
            #pragma unroll
            for (int j = 0; j < 4; ++j) mx[j] = fmaxf(v[j].x, v[j].y);
            #pragma unroll
            for (int o = 16; o; o >>= 1) {
                #pragma unroll
                for (int j = 0; j < 4; ++j)
                    mx[j] = fmaxf(mx[j], __shfl_xor_sync(0xffffffffu, mx[j], o));
            }
            #pragma unroll
            for (int j = 0; j < 4; ++j)
                e[j] = __expf(v[j].x - mx[j]) + __expf(v[j].y - mx[j]);
            #pragma unroll
            for (int o = 16; o; o >>= 1) {
                #pragma unroll
                for (int j = 0; j < 4; ++j)
                    e[j] += __shfl_xor_sync(0xffffffffu, e[j], o);
            }
            #pragma unroll
            for (int j = 0; j < 4; ++j) {
                float pick = (lbl[j] & 1) ? v[j].y : v[j].x;
                float gv = __shfl_sync(0xffffffffu, pick, lbl[j] >> 1);
                if (lane == 0 && has[j]) ce_acc += (mx[j] + __logf(e[j])) - gv;
            }
        }
    }

    // ---- flush per-class accumulators (one-shot) ----
    const int dbase = lane * 4;
    atomicAdd(&g_sums[(base + 0) * D + dbase + 0], a0.x);
    atomicAdd(&g_sums[(base + 0) * D + dbase + 1], a0.y);
    atomicAdd(&g_sums[(base + 0) * D + dbase + 2], a0.z);
    atomicAdd(&g_sums[(base + 0) * D + dbase + 3], a0.w);
    atomicAdd(&g_sums[(base + 1) * D + dbase + 0], a1.x);
    atomicAdd(&g_sums[(base + 1) * D + dbase + 1], a1.y);
    atomicAdd(&g_sums[(base + 1) * D + dbase + 2], a1.z);
    atomicAdd(&g_sums[(base + 1) * D + dbase + 3], a1.w);
    atomicAdd(&g_sums[(base + 2) * D + dbase + 0], a2.x);
    atomicAdd(&g_sums[(base + 2) * D + dbase + 1], a2.y);
    atomicAdd(&g_sums[(base + 2) * D + dbase + 2], a2.z);
    atomicAdd(&g_sums[(base + 2) * D + dbase + 3], a2.w);
    atomicAdd(&g_sums[(base + 3) * D + dbase + 0], a3.x);
    atomicAdd(&g_sums[(base + 3) * D + dbase + 1], a3.y);
    atomicAdd(&g_sums[(base + 3) * D + dbase + 2], a3.z);
    atomicAdd(&g_sums[(base + 3) * D + dbase + 3], a3.w);
    if (lane == 0) {
        atomicAdd(&g_counts[base + 0], c0); atomicAdd(&g_z2[base + 0], q0);
        atomicAdd(&g_counts[base + 1], c1); atomicAdd(&g_z2[base + 1], q1);
        atomicAdd(&g_counts[base + 2], c2); atomicAdd(&g_z2[base + 2], q2);
        atomicAdd(&g_counts[base + 3], c3); atomicAdd(&g_z2[base + 3], q3);
    }

    // ---- block CE reduce + completion mark ----
    if (lane == 0) s_red[wid] = ce_acc;
    __syncthreads();
    if (tid == 0) {
        float s = 0.0f;
        #pragma unroll
        for (int i = 0; i < THREADS_MAIN / 32; ++i) s += s_red[i];
        atomicAdd(&g_ce, s);
        __threadfence();
        s_rank = atomicAdd(&g_done, 1u);
    }
    __syncthreads();

    // =========== last block: finalize + re-zero scratch ===========
    if (s_rank == GRID_MAIN - 1) {
        __threadfence();  // see all blocks' atomics

        #pragma unroll
        for (int cc = 0; cc < 4; ++cc) {
            int c = base + cc;
            float4 v = ((const float4*)(g_sums + c * D))[lane];
            float dot = v.x*v.x + v.y*v.y + v.z*v.z + v.w*v.w;
            #pragma unroll
            for (int o = 16; o; o >>= 1)
                dot += __shfl_xor_sync(0xffffffffu, dot, o);
            if (lane == 0) {
                float cnt  = g_counts[c];
                float safe = fmaxf(cnt, 1.0f);
                float ssd  = g_z2[c] - dot / safe;
                bool valid = (cnt > 1.0f);
                s_pc[c]     = valid ? (ssd / safe) : 0.0f;
                s_pc[C + c] = valid ? 1.0f : 0.0f;
            }
        }
        __syncthreads();
        if (tid == 0) {
            float sp = 0.0f, nv = 0.0f;
            #pragma unroll
            for (int c = 0; c < C; ++c) { sp += s_pc[c]; nv += s_pc[C + c]; }
            float proto = sp / fmaxf(nv, 1.0f);
            float ce    = g_ce / (float)N;
            out[0] = (1.0f - LAMBDA_PROTO) * ce + LAMBDA_PROTO * proto;
        }

        // re-zero scratch for next graph replay
        for (int i = tid; i < C * D; i += THREADS_MAIN) g_sums[i] = 0.0f;
        if (tid < C) { g_counts[tid] = 0.0f; g_z2[tid] = 0.0f; }
        if (tid == 0) { g_ce = 0.0f; __threadfence(); g_done = 0u; }
    }
}

// ---------------------------------------------------------
extern "C" void kernel_launch(void* const* d_in, const int* in_sizes, int n_in,
                              void* d_out, int out_size) {
    const float* emb          = (const float*)d_in[0];
    const float* logits       = (const float*)d_in[1];
    const unsigned int* lab_w = (const unsigned int*)d_in[2];
    int N = in_sizes[2];

    fused_kernel<<<GRID_MAIN, THREADS_MAIN>>>(emb, logits, lab_w, N, (float*)d_out);
}

// round 9
// speedup vs baseline: 1.6793x; 1.1340x over previous
#include <cuda_runtime.h>
#include <cuda_bf16.h>
#include <math.h>

#define D 128
#define C 64
#define ROWS_PER_TILE 128
#define THREADS_MAIN 512   // 16 warps, each owns 4 classes
#define GRID_MAIN 296      // 2 blocks/SM: exactly one wave on 148 SMs
#define LAMBDA_PROTO 0.5f

// -------- device scratch (zero at module load; last block re-zeroes) --------
__device__ float g_sums[C * D];
__device__ float g_counts[C];
__device__ float g_z2[C];
__device__ float g_ce;
__device__ unsigned int g_done;

#define ACC_ROW(k, xv, inv, z2)                                            \
    do {                                                                   \
        if ((k) == 0) {                                                    \
            a0.x = fmaf((xv).x, (inv), a0.x); a0.y = fmaf((xv).y, (inv), a0.y); \
            a0.z = fmaf((xv).z, (inv), a0.z); a0.w = fmaf((xv).w, (inv), a0.w); \
            c0 += 1.0f; q0 += (z2);                                        \
        } else if ((k) == 1) {                                             \
            a1.x = fmaf((xv).x, (inv), a1.x); a1.y = fmaf((xv).y, (inv), a1.y); \
            a1.z = fmaf((xv).z, (inv), a1.z); a1.w = fmaf((xv).w, (inv), a1.w); \
            c1 += 1.0f; q1 += (z2);                                        \
        } else if ((k) == 2) {                                             \
            a2.x = fmaf((xv).x, (inv), a2.x); a2.y = fmaf((xv).y, (inv), a2.y); \
            a2.z = fmaf((xv).z, (inv), a2.z); a2.w = fmaf((xv).w, (inv), a2.w); \
            c2 += 1.0f; q2 += (z2);                                        \
        } else {                                                           \
            a3.x = fmaf((xv).x, (inv), a3.x); a3.y = fmaf((xv).y, (inv), a3.y); \
            a3.z = fmaf((xv).z, (inv), a3.z); a3.w = fmaf((xv).w, (inv), a3.w); \
            c3 += 1.0f; q3 += (z2);                                        \
        }                                                                  \
    } while (0)

// ---------------------------------------------------------
__global__ __launch_bounds__(THREADS_MAIN, 2)
void fused_kernel(const float* __restrict__ emb,
                  const float* __restrict__ logits,
                  const unsigned int* __restrict__ lab_w, int N,
                  float* __restrict__ out)
{
    __shared__ float s_red[16];
    __shared__ float s_pc[2 * C];
    __shared__ unsigned int s_rank;

    const int tid  = threadIdx.x;
    const int wid  = tid >> 5;
    const int lane = tid & 31;
    const int base = wid * 4;          // warp owns classes [base, base+4)
    const int half = lane >> 4;        // CE: half-warp id (0/1)
    const int hl   = lane & 15;        // CE: lane within half

    // --- per-warp label dtype detection ---
    unsigned probe = lab_w[2 * lane + 1];
    const int lbl64 = (__ballot_sync(0xffffffffu, probe != 0u) == 0u);

    float4 a0 = {0,0,0,0}, a1 = a0, a2 = a0, a3 = a0;
    float  c0 = 0, c1 = 0, c2 = 0, c3 = 0;
    float  q0 = 0, q1 = 0, q2 = 0, q3 = 0;
    float  ce_acc = 0.0f;

    const float4* emb4 = (const float4*)emb;
    const float4* lg4  = (const float4*)logits;   // 16 float4 per row (C=64)
    const int ntiles = (N + ROWS_PER_TILE - 1) / ROWS_PER_TILE;

    // =========== single pass: proto routing + CE per tile ===========
    for (int tile = blockIdx.x; tile < ntiles; tile += GRID_MAIN) {
        const int row0 = tile * ROWS_PER_TILE;

        // ---- proto: ballot ownership over the tile's 128 rows ----
        unsigned long long m128[2];
        {
            unsigned b[4];
            #pragma unroll
            for (int h = 0; h < 4; ++h) {
                int r = row0 + lane + 32 * h;
                int v = (r < N) ? (int)lab_w[lbl64 ? 2 * r : r] : -1;
                b[h] = __ballot_sync(0xffffffffu, (unsigned)(v - base) < 4u);
            }
            m128[0] = (unsigned long long)b[0] | ((unsigned long long)b[1] << 32);
            m128[1] = (unsigned long long)b[2] | ((unsigned long long)b[3] << 32);
        }

        // ---- matched rows, four-at-a-time (4 independent chains) ----
        #pragma unroll
        for (int part = 0; part < 2; ++part) {
            unsigned long long m = m128[part];
            const int pbase = row0 + part * 64;
            while (m) {
                int nb = 0;
                int r[4];
                #pragma unroll
                for (int j = 0; j < 4; ++j) {
                    if (m) {
                        r[j] = pbase + (int)(__ffsll((long long)m) - 1);
                        m &= m - 1;
                        nb = j + 1;
                    } else {
                        r[j] = r[0];
                    }
                }
                int kk[4];
                float4 x[4];
                #pragma unroll
                for (int j = 0; j < 4; ++j) {
                    kk[j] = (int)lab_w[lbl64 ? 2 * r[j] : r[j]] - base;
                    x[j]  = emb4[(size_t)r[j] * (D / 4) + lane];
                }
                float s[4];
                #pragma unroll
                for (int j = 0; j < 4; ++j)
                    s[j] = x[j].x*x[j].x + x[j].y*x[j].y + x[j].z*x[j].z + x[j].w*x[j].w;
                #pragma unroll
                for (int o = 16; o; o >>= 1) {
                    #pragma unroll
                    for (int j = 0; j < 4; ++j)
                        s[j] += __shfl_xor_sync(0xffffffffu, s[j], o);
                }
                #pragma unroll
                for (int j = 0; j < 4; ++j) {
                    if (j < nb) {
                        float inv = rsqrtf(fmaxf(s[j], 1e-24f)); // ==1/max(||x||,1e-12)
                        float z2  = s[j] * inv * inv;
                        ACC_ROW(kk[j], x[j], inv, z2);
                    }
                }
            }
        }

        // ---- CE: half-warp per row, 8 rows/warp/tile (4 units x 2 rows) ----
        {
            float4 v[4]; int lbl[4]; bool has[4];
            #pragma unroll
            for (int u = 0; u < 4; ++u) {
                int r = row0 + wid * 8 + u * 2 + half;
                has[u] = r < N;
                v[u] = has[u] ? lg4[(size_t)r * (C / 4) + hl]
                              : make_float4(0.f, 0.f, 0.f, 0.f);
                lbl[u] = has[u] ? (int)lab_w[lbl64 ? 2 * r : r] : 0;
            }
            float e[4], sel[4];
            #pragma unroll
            for (int u = 0; u < 4; ++u) {
                e[u] = __expf(v[u].x) + __expf(v[u].y)
                     + __expf(v[u].z) + __expf(v[u].w);
                int l = lbl[u];
                float comp = (l & 1) ? ((l & 2) ? v[u].w : v[u].y)
                                     : ((l & 2) ? v[u].z : v[u].x);
                sel[u] = (hl == (l >> 2)) ? comp : 0.0f;
            }
            #pragma unroll
            for (int o = 8; o; o >>= 1) {
                #pragma unroll
                for (int u = 0; u < 4; ++u) {
                    e[u]   += __shfl_xor_sync(0xffffffffu, e[u], o);
                    sel[u] += __shfl_xor_sync(0xffffffffu, sel[u], o);
                }
            }
            if (hl == 0) {
                #pragma unroll
                for (int u = 0; u < 4; ++u)
                    if (has[u]) ce_acc += __logf(e[u]) - sel[u];
            }
        }
    }

    // ---- flush per-class accumulators (one-shot) ----
    const int dbase = lane * 4;
    atomicAdd(&g_sums[(base + 0) * D + dbase + 0], a0.x);
    atomicAdd(&g_sums[(base + 0) * D + dbase + 1], a0.y);
    atomicAdd(&g_sums[(base + 0) * D + dbase + 2], a0.z);
    atomicAdd(&g_sums[(base + 0) * D + dbase + 3], a0.w);
    atomicAdd(&g_sums[(base + 1) * D + dbase + 0], a1.x);
    atomicAdd(&g_sums[(base + 1) * D + dbase + 1], a1.y);
    atomicAdd(&g_sums[(base + 1) * D + dbase + 2], a1.z);
    atomicAdd(&g_sums[(base + 1) * D + dbase + 3], a1.w);
    atomicAdd(&g_sums[(base + 2) * D + dbase + 0], a2.x);
    atomicAdd(&g_sums[(base + 2) * D + dbase + 1], a2.y);
    atomicAdd(&g_sums[(base + 2) * D + dbase + 2], a2.z);
    atomicAdd(&g_sums[(base + 2) * D + dbase + 3], a2.w);
    atomicAdd(&g_sums[(base + 3) * D + dbase + 0], a3.x);
    atomicAdd(&g_sums[(base + 3) * D + dbase + 1], a3.y);
    atomicAdd(&g_sums[(base + 3) * D + dbase + 2], a3.z);
    atomicAdd(&g_sums[(base + 3) * D + dbase + 3], a3.w);
    if (lane == 0) {
        atomicAdd(&g_counts[base + 0], c0); atomicAdd(&g_z2[base + 0], q0);
        atomicAdd(&g_counts[base + 1], c1); atomicAdd(&g_z2[base + 1], q1);
        atomicAdd(&g_counts[base + 2], c2); atomicAdd(&g_z2[base + 2], q2);
        atomicAdd(&g_counts[base + 3], c3); atomicAdd(&g_z2[base + 3], q3);
    }

    // ---- block CE reduce (lanes 0 and 16 hold partials) ----
    ce_acc += __shfl_xor_sync(0xffffffffu, ce_acc, 16);
    if (lane == 0) s_red[wid] = ce_acc;
    __syncthreads();
    if (tid == 0) {
        float s = 0.0f;
        #pragma unroll
        for (int i = 0; i < THREADS_MAIN / 32; ++i) s += s_red[i];
        atomicAdd(&g_ce, s);
        __threadfence();
        s_rank = atomicAdd(&g_done, 1u);
    }
    __syncthreads();

    // =========== last block: finalize + re-zero scratch ===========
    if (s_rank == GRID_MAIN - 1) {
        __threadfence();  // see all blocks' atomics

        #pragma unroll
        for (int cc = 0; cc < 4; ++cc) {
            int c = base + cc;
            float4 v = ((const float4*)(g_sums + c * D))[lane];
            float dot = v.x*v.x + v.y*v.y + v.z*v.z + v.w*v.w;
            #pragma unroll
            for (int o = 16; o; o >>= 1)
                dot += __shfl_xor_sync(0xffffffffu, dot, o);
            if (lane == 0) {
                float cnt  = g_counts[c];
                float safe = fmaxf(cnt, 1.0f);
                float ssd  = g_z2[c] - dot / safe;
                bool valid = (cnt > 1.0f);
                s_pc[c]     = valid ? (ssd / safe) : 0.0f;
                s_pc[C + c] = valid ? 1.0f : 0.0f;
            }
        }
        __syncthreads();
        if (tid == 0) {
            float sp = 0.0f, nv = 0.0f;
            #pragma unroll
            for (int c = 0; c < C; ++c) { sp += s_pc[c]; nv += s_pc[C + c]; }
            float proto = sp / fmaxf(nv, 1.0f);
            float ce    = g_ce / (float)N;
            out[0] = (1.0f - LAMBDA_PROTO) * ce + LAMBDA_PROTO * proto;
        }

        // re-zero scratch for next graph replay
        for (int i = tid; i < C * D; i += THREADS_MAIN) g_sums[i] = 0.0f;
        if (tid < C) { g_counts[tid] = 0.0f; g_z2[tid] = 0.0f; }
        if (tid == 0) { g_ce = 0.0f; __threadfence(); g_done = 0u; }
    }
}

// ---------------------------------------------------------
extern "C" void kernel_launch(void* const* d_in, const int* in_sizes, int n_in,
                              void* d_out, int out_size) {
    const float* emb          = (const float*)d_in[0];
    const float* logits       = (const float*)d_in[1];
    const unsigned int* lab_w = (const unsigned int*)d_in[2];
    int N = in_sizes[2];

    fused_kernel<<<GRID_MAIN, THREADS_MAIN>>>(emb, logits, lab_w, N, (float*)d_out);
}